// round 7
// baseline (speedup 1.0000x reference)
#include <cuda_runtime.h>
#include <cstdint>
#include <math.h>

// ---------------------------------------------------------------------------
// Kernel A: pool + circuit closed form + per-block partial stats; the LAST
//           block to finish (ticket) reduces all partials -> scale/bias.
// Kernel B: pure elementwise normalize (1 float4 per thread).
// ---------------------------------------------------------------------------

#define B_TOTAL 65536
#define IPB     32                      // images per block (kernel A)
#define NB      (B_TOTAL / IPB)         // 2048 blocks in kernel A
#define THREADS 256
#define SROW    148                     // padded smem row (floats)

__device__ __align__(16) float g_part[NB * 8];  // per-block [sum0..3, sumsq0..3]
__device__ __align__(16) float g_sb[8];         // scale[4], bias[4]
__device__ unsigned g_cnt = 0;                  // ticket counter (self-resetting)

__device__ __forceinline__ void cp16(unsigned int saddr, const float4* gptr) {
    asm volatile("cp.async.cg.shared.global [%0], [%1], 16;" :: "r"(saddr), "l"(gptr));
}

__global__ __launch_bounds__(THREADS)
void qfc_kernelA(const float* __restrict__ x,
                 const float* __restrict__ pr,
                 const float* __restrict__ gamma,
                 const float* __restrict__ beta,
                 float* __restrict__ out)
{
    __shared__ __align__(16) float sd[IPB][SROW];
    __shared__ float sz[IPB][4];
    __shared__ unsigned s_islast;
    __shared__ float swarp[8][8];

    const int tid = threadIdx.x;
    const float4* __restrict__ x4 = (const float4*)x;
    const long ib = (long)blockIdx.x * IPB;

    // ---- stage 32 images x 144 floats via cp.async (1152 float4) -----------
#pragma unroll
    for (int it = 0; it < 5; it++) {
        int i = tid + it * THREADS;
        if (i < IPB * 36) {
            int img = i / 36;
            int p   = i - img * 36;
            unsigned int sa = (unsigned int)__cvta_generic_to_shared(&sd[img][p * 4]);
            cp16(sa, &x4[(ib + img) * 144 + p]);
        }
    }
    asm volatile("cp.async.commit_group;");

    const int g = tid & 3;
    const float phi  = pr[g * 2 + 0];
    const float lam  = pr[g * 2 + 1];
    const float clam = __cosf(lam);
    const float k2   = __sinf(lam) * __sinf(phi);

    asm volatile("cp.async.wait_group 0;");
    __syncthreads();

    // pooling + single-qubit closed form: 128 threads = 32 images x 4 groups
    if (tid < IPB * 4) {
        const int img = tid >> 2;
        const float* row = &sd[img][g * 6];
        float a0 = 0.f, a1 = 0.f, a2 = 0.f, a3 = 0.f;
#pragma unroll
        for (int r = 0; r < 6; r++) {
            a0 += row[r * 24 + 0];
            a1 += row[r * 24 + 1];
            a2 += row[r * 24 + 2];
            a3 += row[r * 24 + 3];
            a0 += row[r * 24 + 4];
            a1 += row[r * 24 + 5];
        }
        const float theta = ((a0 + a1) + (a2 + a3)) * (1.f / 36.f);
        float st, ct;
        __sincosf(theta, &st, &ct);
        sz[img][g] = clam * ct + k2 * st;
    }
    __syncthreads();

    // products + raw output write + deterministic warp-0 reduction -> g_part
    if (tid < 32) {
        float4 zz = *(float4*)&sz[tid][0];
        float o0 = zz.x;
        float o1 = o0 * zz.y;
        float o2 = o1 * zz.z;
        float o3 = o2 * zz.w;
        ((float4*)out)[ib + tid] = make_float4(o0, o1, o2, o3);

        float acc[8] = {o0, o1, o2, o3, o0 * o0, o1 * o1, o2 * o2, o3 * o3};
#pragma unroll
        for (int k = 0; k < 8; k++) {
#pragma unroll
            for (int off = 16; off; off >>= 1)
                acc[k] += __shfl_down_sync(0xffffffffu, acc[k], off);
        }
        if (tid == 0) {
            *(float4*)&g_part[blockIdx.x * 8]     = make_float4(acc[0], acc[1], acc[2], acc[3]);
            *(float4*)&g_part[blockIdx.x * 8 + 4] = make_float4(acc[4], acc[5], acc[6], acc[7]);
        }
    }
    __syncthreads();

    // ---- ticket: last block to arrive finalizes the batch stats ------------
    if (tid == 0) {
        __threadfence();                      // publish g_part before ticket
        unsigned old = atomicAdd(&g_cnt, 1);
        s_islast = (old == NB - 1) ? 1u : 0u;
    }
    __syncthreads();
    if (!s_islast) return;

    // last block: deterministic reduction of all 2048 partial records
    {
        const int wrp  = tid >> 5;
        const int lane = tid & 31;
        const float4* __restrict__ p4 = (const float4*)g_part;   // 4096 float4
        float r[8] = {0.f, 0.f, 0.f, 0.f, 0.f, 0.f, 0.f, 0.f};
#pragma unroll
        for (int it = 0; it < NB / THREADS; it++) {               // 8 iters
            int j = tid + it * THREADS;
            float4 s = __ldcg(&p4[j * 2]);
            float4 q = __ldcg(&p4[j * 2 + 1]);
            r[0] += s.x; r[1] += s.y; r[2] += s.z; r[3] += s.w;
            r[4] += q.x; r[5] += q.y; r[6] += q.z; r[7] += q.w;
        }
#pragma unroll
        for (int k = 0; k < 8; k++) {
#pragma unroll
            for (int off = 16; off; off >>= 1)
                r[k] += __shfl_down_sync(0xffffffffu, r[k], off);
        }
        if (lane == 0) {
#pragma unroll
            for (int k = 0; k < 8; k++) swarp[wrp][k] = r[k];
        }
        __syncthreads();
        if (tid < 4) {
            float ss = 0.f, qq = 0.f;
#pragma unroll
            for (int w = 0; w < 8; w++) { ss += swarp[w][tid]; qq += swarp[w][4 + tid]; }
            const float mean = ss * (1.f / (float)B_TOTAL);
            const float ex2  = qq * (1.f / (float)B_TOTAL);
            const float var  = fmaxf(ex2 - mean * mean, 0.f);
            const float inv  = rsqrtf(var + 1e-5f);
            const float sc   = gamma[tid] * inv;
            g_sb[tid]     = sc;
            g_sb[4 + tid] = beta[tid] - mean * sc;
        }
        if (tid == 0) {
            __threadfence();
            g_cnt = 0;                        // reset for next graph replay
        }
    }
}

// ---- Kernel B: pure normalize, 1 float4 per thread --------------------------
__global__ __launch_bounds__(256)
void qfc_kernelB(float* __restrict__ out)
{
    const float4 scv = *(const float4*)&g_sb[0];
    const float4 biv = *(const float4*)&g_sb[4];
    const int i = blockIdx.x * 256 + threadIdx.x;    // 65536 threads total
    float4 v = ((float4*)out)[i];
    v.x = v.x * scv.x + biv.x;
    v.y = v.y * scv.y + biv.y;
    v.z = v.z * scv.z + biv.z;
    v.w = v.w * scv.w + biv.w;
    ((float4*)out)[i] = v;
}

extern "C" void kernel_launch(void* const* d_in, const int* in_sizes, int n_in,
                              void* d_out, int out_size)
{
    const float* x      = (const float*)d_in[0];   // [65536,1,24,24]
    const float* params = (const float*)d_in[1];   // [4,2]
    const float* gamma  = (const float*)d_in[2];   // [4]
    const float* beta   = (const float*)d_in[3];   // [4]
    float* out = (float*)d_out;                    // [65536,4]

    qfc_kernelA<<<NB, THREADS>>>(x, params, gamma, beta, out);
    qfc_kernelB<<<B_TOTAL / 256, 256>>>(out);
}

// round 8
// speedup vs baseline: 1.1363x; 1.1363x over previous
#include <cuda_runtime.h>
#include <cstdint>
#include <math.h>

// ---------------------------------------------------------------------------
// A: pool + circuit closed form -> raw out + per-block partial stats (2048 blk)
// S: 1-block stats finalize -> g_sb (scale/bias)
// C: pure elementwise normalize (256 blk, 1 float4/thread)
// ---------------------------------------------------------------------------

#define B_TOTAL 65536
#define IPB     32                      // images per block (kernel A)
#define NB      (B_TOTAL / IPB)         // 2048 blocks in kernel A
#define THREADS 256
#define SROW    148                     // padded smem row (floats)

__device__ __align__(16) float g_part[NB * 8];  // per-block [sum0..3, sumsq0..3]
__device__ __align__(16) float g_sb[8];         // scale[4], bias[4]

__device__ __forceinline__ void cp16(unsigned int saddr, const float4* gptr) {
    asm volatile("cp.async.cg.shared.global [%0], [%1], 16;" :: "r"(saddr), "l"(gptr));
}

__global__ __launch_bounds__(THREADS)
void qfc_kernelA(const float* __restrict__ x,
                 const float* __restrict__ pr,
                 float* __restrict__ out)
{
    __shared__ __align__(16) float sd[IPB][SROW];
    __shared__ float sz[IPB][4];

    const int tid = threadIdx.x;
    const float4* __restrict__ x4 = (const float4*)x;
    const long ib = (long)blockIdx.x * IPB;

    // ---- stage: two commit groups of 16 images (576 float4 each) ----------
#pragma unroll
    for (int h = 0; h < 2; h++) {
#pragma unroll
        for (int it = 0; it < 3; it++) {
            int i = tid + it * THREADS;
            if (i < 16 * 36) {
                int img = (i / 36) + h * 16;
                int p   = i % 36;
                unsigned int sa = (unsigned int)__cvta_generic_to_shared(&sd[img][p * 4]);
                cp16(sa, &x4[(ib + img) * 144 + p]);
            }
        }
        asm volatile("cp.async.commit_group;");
    }

    const int g = tid & 3;
    const float phi  = pr[g * 2 + 0];
    const float lam  = pr[g * 2 + 1];
    const float clam = __cosf(lam);
    const float k2   = __sinf(lam) * __sinf(phi);

    // ---- group 0 ready: pool images 0-15 while group 1 lands --------------
    asm volatile("cp.async.wait_group 1;");
    __syncthreads();
    if (tid < 64) {
        const int img = tid >> 2;                 // 0..15
        const float* row = &sd[img][g * 6];
        float a0 = 0.f, a1 = 0.f, a2 = 0.f, a3 = 0.f;
#pragma unroll
        for (int r = 0; r < 6; r++) {
            a0 += row[r * 24 + 0];
            a1 += row[r * 24 + 1];
            a2 += row[r * 24 + 2];
            a3 += row[r * 24 + 3];
            a0 += row[r * 24 + 4];
            a1 += row[r * 24 + 5];
        }
        const float theta = ((a0 + a1) + (a2 + a3)) * (1.f / 36.f);
        float st, ct;
        __sincosf(theta, &st, &ct);
        sz[img][g] = clam * ct + k2 * st;
    }

    // ---- group 1 ready: pool images 16-31 ---------------------------------
    asm volatile("cp.async.wait_group 0;");
    __syncthreads();
    if (tid >= 64 && tid < 128) {
        const int img = tid >> 2;                 // 16..31
        const float* row = &sd[img][g * 6];
        float a0 = 0.f, a1 = 0.f, a2 = 0.f, a3 = 0.f;
#pragma unroll
        for (int r = 0; r < 6; r++) {
            a0 += row[r * 24 + 0];
            a1 += row[r * 24 + 1];
            a2 += row[r * 24 + 2];
            a3 += row[r * 24 + 3];
            a0 += row[r * 24 + 4];
            a1 += row[r * 24 + 5];
        }
        const float theta = ((a0 + a1) + (a2 + a3)) * (1.f / 36.f);
        float st, ct;
        __sincosf(theta, &st, &ct);
        sz[img][g] = clam * ct + k2 * st;
    }
    __syncthreads();

    // ---- products + raw out write + deterministic warp-0 reduction --------
    if (tid < 32) {
        float4 zz = *(float4*)&sz[tid][0];
        float o0 = zz.x;
        float o1 = o0 * zz.y;
        float o2 = o1 * zz.z;
        float o3 = o2 * zz.w;
        ((float4*)out)[ib + tid] = make_float4(o0, o1, o2, o3);

        float acc[8] = {o0, o1, o2, o3, o0 * o0, o1 * o1, o2 * o2, o3 * o3};
#pragma unroll
        for (int k = 0; k < 8; k++) {
#pragma unroll
            for (int off = 16; off; off >>= 1)
                acc[k] += __shfl_down_sync(0xffffffffu, acc[k], off);
        }
        if (tid == 0) {
            *(float4*)&g_part[blockIdx.x * 8]     = make_float4(acc[0], acc[1], acc[2], acc[3]);
            *(float4*)&g_part[blockIdx.x * 8 + 4] = make_float4(acc[4], acc[5], acc[6], acc[7]);
        }
    }
}

// ---- S: single-block stats finalize -> g_sb --------------------------------
__global__ __launch_bounds__(256)
void qfc_kernelS(const float* __restrict__ gamma,
                 const float* __restrict__ beta)
{
    __shared__ float swarp[8][8];
    const int tid  = threadIdx.x;
    const int wrp  = tid >> 5;
    const int lane = tid & 31;

    const float4* __restrict__ p4 = (const float4*)g_part;   // 4096 float4
    float r[8] = {0.f, 0.f, 0.f, 0.f, 0.f, 0.f, 0.f, 0.f};
#pragma unroll
    for (int it = 0; it < NB / 256; it++) {                   // 8 iters
        int j = tid + it * 256;
        float4 s = __ldcg(&p4[j * 2]);
        float4 q = __ldcg(&p4[j * 2 + 1]);
        r[0] += s.x; r[1] += s.y; r[2] += s.z; r[3] += s.w;
        r[4] += q.x; r[5] += q.y; r[6] += q.z; r[7] += q.w;
    }
#pragma unroll
    for (int k = 0; k < 8; k++) {
#pragma unroll
        for (int off = 16; off; off >>= 1)
            r[k] += __shfl_down_sync(0xffffffffu, r[k], off);
    }
    if (lane == 0) {
#pragma unroll
        for (int k = 0; k < 8; k++) swarp[wrp][k] = r[k];
    }
    __syncthreads();

    if (tid < 4) {
        float ss = 0.f, qq = 0.f;
#pragma unroll
        for (int w = 0; w < 8; w++) { ss += swarp[w][tid]; qq += swarp[w][4 + tid]; }
        const float mean = ss * (1.f / (float)B_TOTAL);
        const float ex2  = qq * (1.f / (float)B_TOTAL);
        const float var  = fmaxf(ex2 - mean * mean, 0.f);
        const float inv  = rsqrtf(var + 1e-5f);
        const float sc   = gamma[tid] * inv;
        g_sb[tid]     = sc;
        g_sb[4 + tid] = beta[tid] - mean * sc;
    }
}

// ---- C: pure normalize, 1 float4 per thread --------------------------------
__global__ __launch_bounds__(256)
void qfc_kernelC(float* __restrict__ out)
{
    const float4 scv = *(const float4*)&g_sb[0];
    const float4 biv = *(const float4*)&g_sb[4];
    const int i = blockIdx.x * 256 + threadIdx.x;    // 65536 threads total
    float4 v = ((float4*)out)[i];
    v.x = v.x * scv.x + biv.x;
    v.y = v.y * scv.y + biv.y;
    v.z = v.z * scv.z + biv.z;
    v.w = v.w * scv.w + biv.w;
    ((float4*)out)[i] = v;
}

extern "C" void kernel_launch(void* const* d_in, const int* in_sizes, int n_in,
                              void* d_out, int out_size)
{
    const float* x      = (const float*)d_in[0];   // [65536,1,24,24]
    const float* params = (const float*)d_in[1];   // [4,2]
    const float* gamma  = (const float*)d_in[2];   // [4]
    const float* beta   = (const float*)d_in[3];   // [4]
    float* out = (float*)d_out;                    // [65536,4]

    qfc_kernelA<<<NB, THREADS>>>(x, params, out);
    qfc_kernelS<<<1, 256>>>(gamma, beta);
    qfc_kernelC<<<B_TOTAL / 256, 256>>>(out);
}